// round 3
// baseline (speedup 1.0000x reference)
#include <cuda_runtime.h>
#include <math.h>

#define BB 2
#define CC 256
#define PP 2304      // H*W
#define KDIM 256
#define CLSN 20
#define NKEY 2324    // CLS + NT
#define NHEAD 8
#define HDIM 32
#define FFDIM 1024

// ---------------- scratch (device globals, no allocation) ----------------
__device__ float g_xq [BB*PP*CC];        // transposed x_query (B,P,C)
__device__ float g_qin[BB*PP*CC];        // LN1(xq)
__device__ float g_kin[BB*NKEY*KDIM];    // LN2(x_key)
__device__ float g_q  [BB*PP*CC];        // qin @ Wq
__device__ float g_kv [BB*NKEY*2*CC];    // kin @ Wkv  (B,N,512): k at [0:256), v at [256:512)
__device__ float g_ctx[BB*PP*CC];        // attention output (B,P,C)
__device__ float g_xq2[BB*PP*CC];        // xq + ctx@Wp + bp
__device__ float g_ln2[BB*PP*CC];        // LN3(xq2)
__device__ float g_hb [BB*PP*FFDIM];     // gelu(ln2@W1+bf1)
__device__ float g_y  [BB*PP*CC];        // xq2 + hb@W2 + bf2

// ---------------- helpers ----------------
__device__ __forceinline__ float wsum(float v){
  #pragma unroll
  for (int o=16;o>0;o>>=1) v += __shfl_xor_sync(0xffffffffu, v, o);
  return v;
}
__device__ __forceinline__ float wmax(float v){
  #pragma unroll
  for (int o=16;o>0;o>>=1) v = fmaxf(v, __shfl_xor_sync(0xffffffffu, v, o));
  return v;
}

// exp(x) for x <= 0, FMA-pipe only (no MUFU). ~1e-6 rel error.
__device__ __forceinline__ float fexp(float x){
  x = fmaxf(x, -80.0f);
  float y = x * 1.4426950408889634f;     // log2(e)
  float r = y + 12582912.0f;             // round-to-nearest-int trick (1.5*2^23)
  float n = r - 12582912.0f;
  float t = (y - n) * 0.6931471805599453f; // f*ln2, f in [-0.5,0.5]
  int   i = __float_as_int(r) - 0x4B400000;
  float p = 8.3333338e-3f;               // 1/120
  p = fmaf(p, t, 4.1666668e-2f);         // 1/24
  p = fmaf(p, t, 1.6666667e-1f);         // 1/6
  p = fmaf(p, t, 0.5f);
  p = fmaf(p, t, 1.0f);
  p = fmaf(p, t, 1.0f);
  return p * __int_as_float((i + 127) << 23);
}
// exp(x) for x in [0,1], degree-7 Taylor (~1e-5 rel error)
__device__ __forceinline__ float exp01(float x){
  float p = 1.9841270e-4f;               // 1/5040
  p = fmaf(p, x, 1.3888889e-3f);         // 1/720
  p = fmaf(p, x, 8.3333338e-3f);         // 1/120
  p = fmaf(p, x, 4.1666668e-2f);         // 1/24
  p = fmaf(p, x, 1.6666667e-1f);         // 1/6
  p = fmaf(p, x, 0.5f);
  p = fmaf(p, x, 1.0f);
  p = fmaf(p, x, 1.0f);
  return p;
}
__device__ __forceinline__ float gelu_exact(float x){
  return 0.5f * x * (1.0f + erff(x * 0.70710678118654752f));
}

// ---------------- transpose: in (B,R,Cd) -> out (B,Cd,R) ----------------
__global__ void k_transpose(const float* __restrict__ in, float* __restrict__ out,
                            int R, int Cd){
  __shared__ float tile[32][33];
  int b = blockIdx.z;
  int r0 = blockIdx.y * 32, c0 = blockIdx.x * 32;
  const float* pin = in + (size_t)b * R * Cd;
  float* pout = out + (size_t)b * R * Cd;
  #pragma unroll
  for (int i = threadIdx.y; i < 32; i += 8){
    int r = r0 + i, c = c0 + threadIdx.x;
    if (r < R && c < Cd) tile[i][threadIdx.x] = pin[(size_t)r * Cd + c];
  }
  __syncthreads();
  #pragma unroll
  for (int i = threadIdx.y; i < 32; i += 8){
    int c = c0 + i, r = r0 + threadIdx.x;
    if (c < Cd && r < R) pout[(size_t)c * R + r] = tile[threadIdx.x][i];
  }
}

// ---------------- LayerNorm over last dim 256, one warp per row ----------------
__global__ void k_ln(const float* __restrict__ in, float* __restrict__ out,
                     const float* __restrict__ g, const float* __restrict__ be, int rows){
  int gw = (blockIdx.x * blockDim.x + threadIdx.x) >> 5;
  int lane = threadIdx.x & 31;
  if (gw >= rows) return;
  const float4* p = (const float4*)(in + (size_t)gw * 256);
  float4 a = p[lane];
  float4 b = p[lane + 32];
  float s  = a.x+a.y+a.z+a.w + b.x+b.y+b.z+b.w;
  float ss = a.x*a.x+a.y*a.y+a.z*a.z+a.w*a.w + b.x*b.x+b.y*b.y+b.z*b.z+b.w*b.w;
  s = wsum(s); ss = wsum(ss);
  float mean = s * (1.0f/256.0f);
  float var  = ss * (1.0f/256.0f) - mean*mean;
  float inv  = rsqrtf(var + 1e-5f);
  const float4* g4 = (const float4*)g;
  const float4* b4 = (const float4*)be;
  float4 ga = g4[lane], gb = g4[lane+32];
  float4 ba = b4[lane], bb = b4[lane+32];
  float4 o1, o2;
  o1.x = (a.x-mean)*inv*ga.x + ba.x;  o1.y = (a.y-mean)*inv*ga.y + ba.y;
  o1.z = (a.z-mean)*inv*ga.z + ba.z;  o1.w = (a.w-mean)*inv*ga.w + ba.w;
  o2.x = (b.x-mean)*inv*gb.x + bb.x;  o2.y = (b.y-mean)*inv*gb.y + bb.y;
  o2.z = (b.z-mean)*inv*gb.z + bb.z;  o2.w = (b.w-mean)*inv*gb.w + bb.w;
  float4* po = (float4*)(out + (size_t)gw * 256);
  po[lane] = o1; po[lane + 32] = o2;
}

// ---------------- generic fp32 GEMM: C = A(M,K) @ B(K,N) + epilogue ----------------
// MODE 0: plain    MODE 1: + bias[col] + resid[idx]    MODE 2: gelu(. + bias[col])
template<int MODE>
__global__ void __launch_bounds__(256) k_gemm(
    const float* __restrict__ A, const float* __restrict__ Bw,
    float* __restrict__ Co, const float* __restrict__ bias,
    const float* __restrict__ resid, int M, int K, int Nn){
  __shared__ float As[16][64];
  __shared__ float Bs[16][64];
  int bm = blockIdx.y * 64, bn = blockIdx.x * 64;
  int tid = threadIdx.x;
  int tx = tid & 15, ty = tid >> 4;
  int arow = tid >> 2, ac = (tid & 3) * 4;
  int brow = tid >> 4, bc = (tid & 15) * 4;
  float acc[4][4];
  #pragma unroll
  for (int i=0;i<4;i++)
    #pragma unroll
    for (int j=0;j<4;j++) acc[i][j]=0.f;
  for (int k0 = 0; k0 < K; k0 += 16){
    float4 av = make_float4(0.f,0.f,0.f,0.f);
    if (bm + arow < M) av = *(const float4*)(A + (size_t)(bm+arow)*K + k0 + ac);
    As[ac+0][arow]=av.x; As[ac+1][arow]=av.y; As[ac+2][arow]=av.z; As[ac+3][arow]=av.w;
    *(float4*)&Bs[brow][bc] = *(const float4*)(Bw + (size_t)(k0+brow)*Nn + bn + bc);
    __syncthreads();
    #pragma unroll
    for (int kk=0; kk<16; kk++){
      float4 a4 = *(const float4*)&As[kk][ty*4];
      float4 b4 = *(const float4*)&Bs[kk][tx*4];
      float aa[4] = {a4.x,a4.y,a4.z,a4.w};
      float bb2[4] = {b4.x,b4.y,b4.z,b4.w};
      #pragma unroll
      for (int i=0;i<4;i++)
        #pragma unroll
        for (int j=0;j<4;j++) acc[i][j] = fmaf(aa[i], bb2[j], acc[i][j]);
    }
    __syncthreads();
  }
  #pragma unroll
  for (int i=0;i<4;i++){
    int row = bm + ty*4 + i;
    if (row >= M) continue;
    #pragma unroll
    for (int j=0;j<4;j++){
      int col = bn + tx*4 + j;
      size_t idx = (size_t)row * Nn + col;
      float v = acc[i][j];
      if (MODE == 1) v += bias[col] + resid[idx];
      if (MODE == 2) v = gelu_exact(v + bias[col]);
      Co[idx] = v;
    }
  }
}

// ---------------- fused attention ----------------
// grid (PP/4, NHEAD, BB), block 128 (4 warps = 4 query rows).
// Full score row (2324 fp32) kept in smem; mask read exactly once; both softmax
// stages use FMA-pipe polynomial exp; AV fused.
__global__ void __launch_bounds__(128) k_attn(const float* __restrict__ mask){
  __shared__ float s_s[4][2336];
  __shared__ float s_k[32][33];
  const float SC = 0.17677669529663687f;
  int b = blockIdx.z, h = blockIdx.y;
  int m0 = blockIdx.x * 4;
  int tid = threadIdx.x;
  int mi = tid >> 5, lane = tid & 31;
  // hoist q row into registers (warp-uniform broadcast loads)
  float qreg[HDIM];
  {
    const float* qp = g_q + ((size_t)(b*PP + m0 + mi))*CC + h*HDIM;
    #pragma unroll
    for (int d=0; d<HDIM; d++) qreg[d] = qp[d];
  }
  const float* kvb = g_kv + (size_t)b * NKEY * 512;
  int lr = tid >> 2, lc = (tid & 3) * 8;
  // ---- phase 1: S = q.kT * scale ----
  for (int j0 = 0; j0 < NKEY; j0 += 32){
    int j = j0 + lr;
    if (j < NKEY){
      const float* kp = kvb + (size_t)j*512 + h*HDIM + lc;
      float4 v0 = *(const float4*)kp;
      float4 v1 = *(const float4*)(kp+4);
      s_k[lr][lc+0]=v0.x; s_k[lr][lc+1]=v0.y; s_k[lr][lc+2]=v0.z; s_k[lr][lc+3]=v0.w;
      s_k[lr][lc+4]=v1.x; s_k[lr][lc+5]=v1.y; s_k[lr][lc+6]=v1.z; s_k[lr][lc+7]=v1.w;
    } else {
      #pragma unroll
      for (int i=0;i<8;i++) s_k[lr][lc+i]=0.f;
    }
    __syncthreads();
    float acc = 0.f;
    #pragma unroll
    for (int d=0; d<HDIM; d++) acc = fmaf(qreg[d], s_k[lane][d], acc);
    s_s[mi][j0 + lane] = acc * SC;
    __syncthreads();
  }
  // ---- phase 2: segment softmaxes (warp mi owns row m0+mi) ----
  float* srow = s_s[mi];
  int m = m0 + mi;
  float v1 = (lane < CLSN) ? srow[lane] : -1e30f;
  float m1 = wmax(v1);
  float e1 = (lane < CLSN) ? fexp(v1 - m1) : 0.f;
  if (lane < CLSN) srow[lane] = e1;
  float den1 = wsum(e1);
  float mx = -1e30f;
  for (int j2 = CLSN + lane; j2 < NKEY; j2 += 32) mx = fmaxf(mx, srow[j2]);
  mx = wmax(mx);
  float den2 = 0.f;
  for (int j2 = CLSN + lane; j2 < NKEY; j2 += 32){
    float e = fexp(srow[j2] - mx);
    srow[j2] = e;
    den2 += e;
  }
  den2 = wsum(den2);
  float inv1 = 1.f/den1, inv2 = 1.f/den2;
  // ---- phase 3: mask + second softmax (exp of probs in [0,1]) ----
  const float* mrow = mask + ((size_t)(b*NHEAD + h)*NKEY + (size_t)(CLSN + m)) * NKEY;
  float denf = 0.f;
  for (int j2 = lane; j2 < NKEY; j2 += 32){
    float pv = srow[j2] * (j2 < CLSN ? inv1 : inv2);
    float t = (mrow[j2] < 0.3f) ? 0.f : exp01(pv);
    denf += t;
    srow[j2] = t;
  }
  denf = wsum(denf);
  float invf = 1.f/denf;
  // ---- phase 4: AV (lanes: 8 d-groups x 4 j-streams) ----
  int dq = lane & 7, jq = lane >> 3;
  float4 a4 = make_float4(0.f,0.f,0.f,0.f);
  const float* vb = kvb + 256 + h*HDIM + dq*4;
  for (int j2 = jq; j2 < NKEY; j2 += 4){   // NKEY % 4 == 0
    float t = srow[j2];
    float4 vv = *(const float4*)(vb + (size_t)j2 * 512);
    a4.x = fmaf(t, vv.x, a4.x);
    a4.y = fmaf(t, vv.y, a4.y);
    a4.z = fmaf(t, vv.z, a4.z);
    a4.w = fmaf(t, vv.w, a4.w);
  }
  #pragma unroll
  for (int o = 8; o <= 16; o <<= 1){
    a4.x += __shfl_xor_sync(0xffffffffu, a4.x, o);
    a4.y += __shfl_xor_sync(0xffffffffu, a4.y, o);
    a4.z += __shfl_xor_sync(0xffffffffu, a4.z, o);
    a4.w += __shfl_xor_sync(0xffffffffu, a4.w, o);
  }
  if (jq == 0){
    float4 o4 = make_float4(a4.x*invf, a4.y*invf, a4.z*invf, a4.w*invf);
    *(float4*)(g_ctx + ((size_t)(b*PP + m))*CC + h*HDIM + dq*4) = o4;
  }
}

// ---------------- launch ----------------
extern "C" void kernel_launch(void* const* d_in, const int* in_sizes, int n_in,
                              void* d_out, int out_size){
  const float* x_query = (const float*)d_in[0];
  const float* x_key   = (const float*)d_in[1];
  const float* mask    = (const float*)d_in[2];
  const float* g1  = (const float*)d_in[3];
  const float* be1 = (const float*)d_in[4];
  const float* g2  = (const float*)d_in[5];
  const float* be2 = (const float*)d_in[6];
  const float* g3  = (const float*)d_in[7];
  const float* be3 = (const float*)d_in[8];
  const float* Wq  = (const float*)d_in[9];
  const float* Wkv = (const float*)d_in[10];
  // d_in[11] = Wcls: provably unused (CLS query rows are sliced away after Wp)
  const float* Wp  = (const float*)d_in[12];
  const float* bp  = (const float*)d_in[13];
  const float* W1  = (const float*)d_in[14];
  const float* bf1 = (const float*)d_in[15];
  const float* W2  = (const float*)d_in[16];
  const float* bf2 = (const float*)d_in[17];
  float* out = (float*)d_out;

  float *xq,*qin,*kin,*q,*kv,*ctx,*xq2,*ln2,*hb,*y;
  cudaGetSymbolAddress((void**)&xq,  g_xq);
  cudaGetSymbolAddress((void**)&qin, g_qin);
  cudaGetSymbolAddress((void**)&kin, g_kin);
  cudaGetSymbolAddress((void**)&q,   g_q);
  cudaGetSymbolAddress((void**)&kv,  g_kv);
  cudaGetSymbolAddress((void**)&ctx, g_ctx);
  cudaGetSymbolAddress((void**)&xq2, g_xq2);
  cudaGetSymbolAddress((void**)&ln2, g_ln2);
  cudaGetSymbolAddress((void**)&hb,  g_hb);
  cudaGetSymbolAddress((void**)&y,   g_y);

  // 1. (B,C,P) -> (B,P,C)
  k_transpose<<<dim3(PP/32, CC/32, BB), dim3(32,8)>>>(x_query, xq, CC, PP);
  // 2-3. LayerNorms
  k_ln<<<(BB*PP)/8, 256>>>(xq, qin, g1, be1, BB*PP);
  k_ln<<<(BB*NKEY+7)/8, 256>>>(x_key, kin, g2, be2, BB*NKEY);
  // 4-5. q / kv projections
  k_gemm<0><<<dim3(CC/64,      (BB*PP)/64),     256>>>(qin, Wq,  q,  nullptr, nullptr, BB*PP,   CC,   CC);
  k_gemm<0><<<dim3((2*CC)/64,  (BB*NKEY+63)/64),256>>>(kin, Wkv, kv, nullptr, nullptr, BB*NKEY, KDIM, 2*CC);
  // 6. fused attention (CLS query rows skipped: their outputs are sliced away)
  k_attn<<<dim3(PP/4, NHEAD, BB), 128>>>(mask);
  // 7. ctx@Wp + bp + xq  -> xq2
  k_gemm<1><<<dim3(CC/64, (BB*PP)/64), 256>>>(ctx, Wp, xq2, bp, xq, BB*PP, CC, CC);
  // 8. LN3
  k_ln<<<(BB*PP)/8, 256>>>(xq2, ln2, g3, be3, BB*PP);
  // 9. gelu(ln2@W1 + bf1)
  k_gemm<2><<<dim3(FFDIM/64, (BB*PP)/64), 256>>>(ln2, W1, hb, bf1, nullptr, BB*PP, CC, FFDIM);
  // 10. xq2 + hb@W2 + bf2
  k_gemm<1><<<dim3(CC/64, (BB*PP)/64), 256>>>(hb, W2, y, bf2, xq2, BB*PP, FFDIM, CC);
  // 11. (B,P,C) -> (B,C,P) = (B,C,H,W)
  k_transpose<<<dim3(CC/32, PP/32, BB), dim3(32,8)>>>(y, out, PP, CC);
}

// round 8
// speedup vs baseline: 1.3984x; 1.3984x over previous
#include <cuda_runtime.h>
#include <math.h>

#define BB 2
#define CC 256
#define PP 2304      // H*W
#define KDIM 256
#define CLSN 20
#define NKEY 2324    // CLS + NT
#define NHEAD 8
#define HDIM 32
#define FFDIM 1024
#define SN 2336      // padded score row stride (73*32)

// ---------------- scratch (device globals, no allocation) ----------------
__device__ float g_xq [BB*PP*CC];        // transposed x_query (B,P,C)
__device__ float g_qin[BB*PP*CC];        // LN1(xq)
__device__ float g_kin[BB*NKEY*KDIM];    // LN2(x_key)
__device__ float g_q  [BB*PP*CC];        // qin @ Wq
__device__ float g_kv [BB*NKEY*2*CC + 16*512]; // kin @ Wkv (+pad rows, zero)
__device__ float g_ctx[BB*PP*CC];        // attention output (B,P,C)
__device__ float g_xq2[BB*PP*CC];        // xq + ctx@Wp + bp
__device__ float g_ln2[BB*PP*CC];        // LN3(xq2)
__device__ float g_hb [BB*PP*FFDIM];     // gelu(ln2@W1+bf1)
__device__ float g_y  [BB*PP*CC];        // xq2 + hb@W2 + bf2
__device__ float g_S  [(size_t)BB*NHEAD*PP*SN];  // scores / probs (345MB)

// ---------------- helpers ----------------
__device__ __forceinline__ float wsum(float v){
  #pragma unroll
  for (int o=16;o>0;o>>=1) v += __shfl_xor_sync(0xffffffffu, v, o);
  return v;
}
__device__ __forceinline__ float wmax(float v){
  #pragma unroll
  for (int o=16;o>0;o>>=1) v = fmaxf(v, __shfl_xor_sync(0xffffffffu, v, o));
  return v;
}
// exp(x) for x <= 0, FMA-pipe only (no MUFU). ~1e-6 rel error.
__device__ __forceinline__ float fexp(float x){
  x = fmaxf(x, -80.0f);
  float y = x * 1.4426950408889634f;
  float r = y + 12582912.0f;
  float n = r - 12582912.0f;
  float t = (y - n) * 0.6931471805599453f;
  int   i = __float_as_int(r) - 0x4B400000;
  float p = 8.3333338e-3f;
  p = fmaf(p, t, 4.1666668e-2f);
  p = fmaf(p, t, 1.6666667e-1f);
  p = fmaf(p, t, 0.5f);
  p = fmaf(p, t, 1.0f);
  p = fmaf(p, t, 1.0f);
  return p * __int_as_float((i + 127) << 23);
}
// exp(x) for x in [0,1]
__device__ __forceinline__ float exp01(float x){
  float p = 1.9841270e-4f;
  p = fmaf(p, x, 1.3888889e-3f);
  p = fmaf(p, x, 8.3333338e-3f);
  p = fmaf(p, x, 4.1666668e-2f);
  p = fmaf(p, x, 1.6666667e-1f);
  p = fmaf(p, x, 0.5f);
  p = fmaf(p, x, 1.0f);
  p = fmaf(p, x, 1.0f);
  return p;
}
__device__ __forceinline__ float gelu_exact(float x){
  return 0.5f * x * (1.0f + erff(x * 0.70710678118654752f));
}

// ---------------- transpose: in (B,R,Cd) -> out (B,Cd,R) ----------------
__global__ void k_transpose(const float* __restrict__ in, float* __restrict__ out,
                            int R, int Cd){
  __shared__ float tile[32][33];
  int b = blockIdx.z;
  int r0 = blockIdx.y * 32, c0 = blockIdx.x * 32;
  const float* pin = in + (size_t)b * R * Cd;
  float* pout = out + (size_t)b * R * Cd;
  #pragma unroll
  for (int i = threadIdx.y; i < 32; i += 8){
    int r = r0 + i, c = c0 + threadIdx.x;
    if (r < R && c < Cd) tile[i][threadIdx.x] = pin[(size_t)r * Cd + c];
  }
  __syncthreads();
  #pragma unroll
  for (int i = threadIdx.y; i < 32; i += 8){
    int c = c0 + i, r = r0 + threadIdx.x;
    if (c < Cd && r < R) pout[(size_t)c * R + r] = tile[threadIdx.x][i];
  }
}

// ---------------- LayerNorm over last dim 256, one warp per row ----------------
__global__ void k_ln(const float* __restrict__ in, float* __restrict__ out,
                     const float* __restrict__ g, const float* __restrict__ be, int rows){
  int gw = (blockIdx.x * blockDim.x + threadIdx.x) >> 5;
  int lane = threadIdx.x & 31;
  if (gw >= rows) return;
  const float4* p = (const float4*)(in + (size_t)gw * 256);
  float4 a = p[lane];
  float4 b = p[lane + 32];
  float s  = a.x+a.y+a.z+a.w + b.x+b.y+b.z+b.w;
  float ss = a.x*a.x+a.y*a.y+a.z*a.z+a.w*a.w + b.x*b.x+b.y*b.y+b.z*b.z+b.w*b.w;
  s = wsum(s); ss = wsum(ss);
  float mean = s * (1.0f/256.0f);
  float var  = ss * (1.0f/256.0f) - mean*mean;
  float inv  = rsqrtf(var + 1e-5f);
  const float4* g4 = (const float4*)g;
  const float4* b4 = (const float4*)be;
  float4 ga = g4[lane], gb = g4[lane+32];
  float4 ba = b4[lane], bb = b4[lane+32];
  float4 o1, o2;
  o1.x = (a.x-mean)*inv*ga.x + ba.x;  o1.y = (a.y-mean)*inv*ga.y + ba.y;
  o1.z = (a.z-mean)*inv*ga.z + ba.z;  o1.w = (a.w-mean)*inv*ga.w + ba.w;
  o2.x = (b.x-mean)*inv*gb.x + bb.x;  o2.y = (b.y-mean)*inv*gb.y + bb.y;
  o2.z = (b.z-mean)*inv*gb.z + bb.z;  o2.w = (b.w-mean)*inv*gb.w + bb.w;
  float4* po = (float4*)(out + (size_t)gw * 256);
  po[lane] = o1; po[lane + 32] = o2;
}

// ---------------- 128x128 GEMM, 8x8 micro, double-buffered ----------------
// C = A(M,K) @ B(K,N) + epilogue.  N multiple of 128, K multiple of 16, M guarded.
// MODE 0: plain    MODE 1: + bias[col] + resid[idx]    MODE 2: gelu(. + bias[col])
template<int MODE>
__global__ void __launch_bounds__(256) k_gemm128(
    const float* __restrict__ A, const float* __restrict__ Bw,
    float* __restrict__ Co, const float* __restrict__ bias,
    const float* __restrict__ resid, int M, int K, int Nn){
  __shared__ float As[2][16][132];   // transposed: As[k][m]
  __shared__ float Bs[2][16][128];   // Bs[k][n]
  const int bm = blockIdx.y * 128, bn = blockIdx.x * 128;
  const int t = threadIdx.x;
  const int tx = t & 15, ty = t >> 4;
  // A loader coords (2 float4 per thread over 512)
  const int ar0 = t >> 1;                 // wrong mapping avoided: use idx math below
  (void)ar0;
  const int KT = K >> 4;
  float4 pa0, pa1, pb0, pb1;
  const float4 zf4 = make_float4(0.f,0.f,0.f,0.f);

  auto ldA = [&](int kt, int idx, float4& v){
    int row = idx >> 2, kq = idx & 3;
    int gr = bm + row;
    v = (gr < M) ? *(const float4*)(A + (size_t)gr*K + kt*16 + kq*4) : zf4;
  };
  auto ldB = [&](int kt, int idx, float4& v){
    int kr = idx >> 5, col = (idx & 31) * 4;
    v = *(const float4*)(Bw + (size_t)(kt*16 + kr)*Nn + bn + col);
  };
  auto stA = [&](int buf, int idx, const float4& v){
    int row = idx >> 2, kq = (idx & 3) * 4;
    As[buf][kq+0][row] = v.x; As[buf][kq+1][row] = v.y;
    As[buf][kq+2][row] = v.z; As[buf][kq+3][row] = v.w;
  };
  auto stB = [&](int buf, int idx, const float4& v){
    int kr = idx >> 5, col = (idx & 31) * 4;
    *(float4*)&Bs[buf][kr][col] = v;
  };

  float acc[8][8];
  #pragma unroll
  for (int i=0;i<8;i++)
    #pragma unroll
    for (int j=0;j<8;j++) acc[i][j] = 0.f;

  ldA(0, t, pa0); ldA(0, t+256, pa1);
  ldB(0, t, pb0); ldB(0, t+256, pb1);
  stA(0, t, pa0); stA(0, t+256, pa1);
  stB(0, t, pb0); stB(0, t+256, pb1);
  __syncthreads();

  for (int kt = 0; kt < KT; kt++){
    int buf = kt & 1;
    if (kt + 1 < KT){
      ldA(kt+1, t, pa0); ldA(kt+1, t+256, pa1);
      ldB(kt+1, t, pb0); ldB(kt+1, t+256, pb1);
    }
    #pragma unroll
    for (int kk = 0; kk < 16; kk++){
      float4 a0 = *(const float4*)&As[buf][kk][ty*8];
      float4 a1 = *(const float4*)&As[buf][kk][ty*8+4];
      float4 b0 = *(const float4*)&Bs[buf][kk][tx*8];
      float4 b1 = *(const float4*)&Bs[buf][kk][tx*8+4];
      float av[8] = {a0.x,a0.y,a0.z,a0.w,a1.x,a1.y,a1.z,a1.w};
      float bv[8] = {b0.x,b0.y,b0.z,b0.w,b1.x,b1.y,b1.z,b1.w};
      #pragma unroll
      for (int i=0;i<8;i++)
        #pragma unroll
        for (int j=0;j<8;j++) acc[i][j] = fmaf(av[i], bv[j], acc[i][j]);
    }
    if (kt + 1 < KT){
      int nb = buf ^ 1;
      stA(nb, t, pa0); stA(nb, t+256, pa1);
      stB(nb, t, pb0); stB(nb, t+256, pb1);
      __syncthreads();
    }
  }

  // epilogue
  float4 bia0 = zf4, bia1 = zf4;
  if (MODE != 0){
    bia0 = *(const float4*)(bias + bn + tx*8);
    bia1 = *(const float4*)(bias + bn + tx*8 + 4);
  }
  #pragma unroll
  for (int i=0;i<8;i++){
    int gr = bm + ty*8 + i;
    if (gr >= M) continue;
    size_t base = (size_t)gr * Nn + bn + tx*8;
    float4 v0 = make_float4(acc[i][0],acc[i][1],acc[i][2],acc[i][3]);
    float4 v1 = make_float4(acc[i][4],acc[i][5],acc[i][6],acc[i][7]);
    if (MODE == 1){
      float4 r0 = *(const float4*)(resid + base);
      float4 r1 = *(const float4*)(resid + base + 4);
      v0.x += bia0.x + r0.x; v0.y += bia0.y + r0.y; v0.z += bia0.z + r0.z; v0.w += bia0.w + r0.w;
      v1.x += bia1.x + r1.x; v1.y += bia1.y + r1.y; v1.z += bia1.z + r1.z; v1.w += bia1.w + r1.w;
    } else if (MODE == 2){
      v0.x = gelu_exact(v0.x + bia0.x); v0.y = gelu_exact(v0.y + bia0.y);
      v0.z = gelu_exact(v0.z + bia0.z); v0.w = gelu_exact(v0.w + bia0.w);
      v1.x = gelu_exact(v1.x + bia1.x); v1.y = gelu_exact(v1.y + bia1.y);
      v1.z = gelu_exact(v1.z + bia1.z); v1.w = gelu_exact(v1.w + bia1.w);
    }
    *(float4*)(Co + base)     = v0;
    *(float4*)(Co + base + 4) = v1;
  }
}

// ---------------- S = scale * Q K^T per (b,h) ----------------
// grid (ceil(NKEY/128)=19, PP/128=18, 16), block 256. Single K-pass (K=32).
__global__ void __launch_bounds__(256) k_sgemm(){
  __shared__ float Qs[32][132];   // Qs[d][m]
  __shared__ float Ks[32][132];   // Ks[d][j]
  const float SC = 0.17677669529663687f;
  int bh = blockIdx.z;
  int b = bh >> 3, h = bh & 7;
  int bm = blockIdx.y * 128, bj = blockIdx.x * 128;
  int t = threadIdx.x;
  // load tiles: 1024 float4 each, 4 per thread
  #pragma unroll
  for (int i=0;i<4;i++){
    int idx = t + i*256;
    int row = idx >> 3, dq = (idx & 7) * 4;
    float4 qv = *(const float4*)(g_q + ((size_t)(b*PP + bm + row))*CC + h*HDIM + dq);
    Qs[dq+0][row]=qv.x; Qs[dq+1][row]=qv.y; Qs[dq+2][row]=qv.z; Qs[dq+3][row]=qv.w;
    int j = bj + row;
    float4 kv = make_float4(0.f,0.f,0.f,0.f);
    if (j < NKEY) kv = *(const float4*)(g_kv + ((size_t)(b*NKEY + j))*512 + h*HDIM + dq);
    Ks[dq+0][row]=kv.x; Ks[dq+1][row]=kv.y; Ks[dq+2][row]=kv.z; Ks[dq+3][row]=kv.w;
  }
  __syncthreads();
  int tx = t & 15, ty = t >> 4;
  float acc[8][8];
  #pragma unroll
  for (int i=0;i<8;i++)
    #pragma unroll
    for (int j=0;j<8;j++) acc[i][j]=0.f;
  #pragma unroll
  for (int d=0; d<32; d++){
    float4 a0 = *(const float4*)&Qs[d][ty*8];
    float4 a1 = *(const float4*)&Qs[d][ty*8+4];
    float4 b0 = *(const float4*)&Ks[d][tx*8];
    float4 b1 = *(const float4*)&Ks[d][tx*8+4];
    float av[8] = {a0.x,a0.y,a0.z,a0.w,a1.x,a1.y,a1.z,a1.w};
    float bv[8] = {b0.x,b0.y,b0.z,b0.w,b1.x,b1.y,b1.z,b1.w};
    #pragma unroll
    for (int i=0;i<8;i++)
      #pragma unroll
      for (int j=0;j<8;j++) acc[i][j] = fmaf(av[i], bv[j], acc[i][j]);
  }
  // store
  bool fast = (bj + 128 <= NKEY);
  #pragma unroll
  for (int i=0;i<8;i++){
    float* srow = g_S + ((size_t)bh*PP + bm + ty*8 + i)*SN + bj + tx*8;
    if (fast){
      *(float4*)srow     = make_float4(acc[i][0]*SC, acc[i][1]*SC, acc[i][2]*SC, acc[i][3]*SC);
      *(float4*)(srow+4) = make_float4(acc[i][4]*SC, acc[i][5]*SC, acc[i][6]*SC, acc[i][7]*SC);
    } else {
      #pragma unroll
      for (int j=0;j<8;j++){
        int col = bj + tx*8 + j;
        if (col < NKEY) srow[j] = acc[i][j]*SC;
      }
    }
  }
}

// ---------------- softmax stages + mask, in place S -> P ----------------
// one warp per (bh, m) row; grid 4608 blocks x 256.
__global__ void __launch_bounds__(256) k_soft(const float* __restrict__ mask){
  int w = (blockIdx.x * 256 + threadIdx.x) >> 5;
  int lane = threadIdx.x & 31;
  int bh = w / PP, m = w - bh * PP;
  float* srow = g_S + ((size_t)bh*PP + m)*SN;
  // pass 1: maxes
  float v1 = (lane < CLSN) ? srow[lane] : -1e30f;
  float m1 = wmax(v1);
  float mx = -1e30f;
  #pragma unroll 4
  for (int it = 0; it < 72; it++) mx = fmaxf(mx, srow[CLSN + it*32 + lane]);
  mx = wmax(mx);
  // pass 2: denominators
  float d1 = (lane < CLSN) ? fexp(v1 - m1) : 0.f;
  float den1 = wsum(d1);
  float d2 = 0.f;
  #pragma unroll 4
  for (int it = 0; it < 72; it++) d2 += fexp(srow[CLSN + it*32 + lane] - mx);
  float den2 = wsum(d2);
  float inv1 = 1.f/den1, inv2 = 1.f/den2;
  // pass 3: probs -> mask -> exp01
  const float* mrow = mask + ((size_t)bh*NKEY + (CLSN + m))*NKEY;
  float dnf = 0.f;
  for (int it = 0; it < 73; it++){
    int j = it*32 + lane;
    float tv = 0.f;
    if (j < NKEY){
      float s = srow[j];
      float pv = (j < CLSN) ? fexp(s - m1)*inv1 : fexp(s - mx)*inv2;
      tv = (mrow[j] < 0.3f) ? 0.f : exp01(pv);
    }
    srow[j] = tv;
    dnf += tv;
  }
  dnf = wsum(dnf);
  float invf = 1.f/dnf;
  // pass 4: normalize (pads stay 0)
  #pragma unroll 4
  for (int it = 0; it < 73; it++){
    int j = it*32 + lane;
    srow[j] *= invf;
  }
}

// ---------------- ctx = P @ V per (b,h) ----------------
// grid (PP/256=9, 16), block 256. Tile 256m x 32n, K-step 32 (73 tiles over SN).
__global__ void __launch_bounds__(256) k_av(){
  __shared__ float Ps[32][260];   // Ps[k][m]
  __shared__ float Vs[32][36];    // Vs[k][d]
  int bh = blockIdx.y;
  int b = bh >> 3, h = bh & 7;
  int bm = blockIdx.x * 256;
  int t = threadIdx.x;
  int r0 = (t >> 3) * 8;          // row group 0..248
  int nx = (t & 7) * 4;           // col group 0..28
  float acc[8][4];
  #pragma unroll
  for (int i=0;i<8;i++)
    #pragma unroll
    for (int j=0;j<4;j++) acc[i][j]=0.f;

  for (int k0 = 0; k0 < SN; k0 += 32){
    // P tile: 256 rows x 32 k = 2048 float4, 8 per thread
    #pragma unroll
    for (int i=0;i<8;i++){
      int idx = t + i*256;
      int row = idx >> 3, kq = (idx & 7) * 4;
      float4 v = *(const float4*)(g_S + ((size_t)bh*PP + bm + row)*SN + k0 + kq);
      Ps[kq+0][row]=v.x; Ps[kq+1][row]=v.y; Ps[kq+2][row]=v.z; Ps[kq+3][row]=v.w;
    }
    // V tile: 32 rows x 32 d = 256 float4, 1 per thread
    {
      int vr = t >> 3, dq = (t & 7) * 4;
      int j = k0 + vr;
      float4 v = make_float4(0.f,0.f,0.f,0.f);
      if (j < NKEY) v = *(const float4*)(g_kv + ((size_t)(b*NKEY + j))*512 + 256 + h*HDIM + dq);
      *(float4*)&Vs[vr][dq] = v;
    }
    __syncthreads();
    #pragma unroll
    for (int kk=0; kk<32; kk++){
      float4 a0 = *(const float4*)&Ps[kk][r0];
      float4 a1 = *(const float4*)&Ps[kk][r0+4];
      float4 bv = *(const float4*)&Vs[kk][nx];
      float av[8] = {a0.x,a0.y,a0.z,a0.w,a1.x,a1.y,a1.z,a1.w};
      #pragma unroll
      for (int i=0;i<8;i++){
        acc[i][0] = fmaf(av[i], bv.x, acc[i][0]);
        acc[i][1] = fmaf(av[i], bv.y, acc[i][1]);
        acc[i][2] = fmaf(av[i], bv.z, acc[i][2]);
        acc[i][3] = fmaf(av[i], bv.w, acc[i][3]);
      }
    }
    __syncthreads();
  }
  #pragma unroll
  for (int i=0;i<8;i++){
    *(float4*)(g_ctx + ((size_t)(b*PP + bm + r0 + i))*CC + h*HDIM + nx) =
        make_float4(acc[i][0], acc[i][1], acc[i][2], acc[i][3]);
  }
}

// ---------------- launch ----------------
extern "C" void kernel_launch(void* const* d_in, const int* in_sizes, int n_in,
                              void* d_out, int out_size){
  const float* x_query = (const float*)d_in[0];
  const float* x_key   = (const float*)d_in[1];
  const float* mask    = (const float*)d_in[2];
  const float* g1  = (const float*)d_in[3];
  const float* be1 = (const float*)d_in[4];
  const float* g2  = (const float*)d_in[5];
  const float* be2 = (const float*)d_in[6];
  const float* g3  = (const float*)d_in[7];
  const float* be3 = (const float*)d_in[8];
  const float* Wq  = (const float*)d_in[9];
  const float* Wkv = (const float*)d_in[10];
  // d_in[11] = Wcls: unused (CLS query rows are sliced away after Wp)
  const float* Wp  = (const float*)d_in[12];
  const float* bp  = (const float*)d_in[13];
  const float* W1  = (const float*)d_in[14];
  const float* bf1 = (const float*)d_in[15];
  const float* W2  = (const float*)d_in[16];
  const float* bf2 = (const float*)d_in[17];
  float* out = (float*)d_out;

  float *xq,*qin,*kin,*q,*kv,*ctx,*xq2,*ln2,*hb,*y;
  cudaGetSymbolAddress((void**)&xq,  g_xq);
  cudaGetSymbolAddress((void**)&qin, g_qin);
  cudaGetSymbolAddress((void**)&kin, g_kin);
  cudaGetSymbolAddress((void**)&q,   g_q);
  cudaGetSymbolAddress((void**)&kv,  g_kv);
  cudaGetSymbolAddress((void**)&ctx, g_ctx);
  cudaGetSymbolAddress((void**)&xq2, g_xq2);
  cudaGetSymbolAddress((void**)&ln2, g_ln2);
  cudaGetSymbolAddress((void**)&hb,  g_hb);
  cudaGetSymbolAddress((void**)&y,   g_y);

  // 1. (B,C,P) -> (B,P,C)
  k_transpose<<<dim3(PP/32, CC/32, BB), dim3(32,8)>>>(x_query, xq, CC, PP);
  // 2-3. LayerNorms
  k_ln<<<(BB*PP)/8, 256>>>(xq, qin, g1, be1, BB*PP);
  k_ln<<<(BB*NKEY+7)/8, 256>>>(x_key, kin, g2, be2, BB*NKEY);
  // 4-5. q / kv projections
  k_gemm128<0><<<dim3(CC/128,    (BB*PP)/128),      256>>>(qin, Wq,  q,  nullptr, nullptr, BB*PP,   CC,   CC);
  k_gemm128<0><<<dim3((2*CC)/128,(BB*NKEY+127)/128),256>>>(kin, Wkv, kv, nullptr, nullptr, BB*NKEY, KDIM, 2*CC);
  // 6a. S = scale Q K^T
  k_sgemm<<<dim3((NKEY+127)/128, PP/128, BB*NHEAD), 256>>>();
  // 6b. softmax stages + mask (in place)
  k_soft<<<(BB*NHEAD*PP)/8, 256>>>(mask);
  // 6c. ctx = P V
  k_av<<<dim3(PP/256, BB*NHEAD), 256>>>();
  // 7. ctx@Wp + bp + xq  -> xq2
  k_gemm128<1><<<dim3(CC/128, (BB*PP)/128), 256>>>(ctx, Wp, xq2, bp, xq, BB*PP, CC, CC);
  // 8. LN3
  k_ln<<<(BB*PP)/8, 256>>>(xq2, ln2, g3, be3, BB*PP);
  // 9. gelu(ln2@W1 + bf1)
  k_gemm128<2><<<dim3(FFDIM/128, (BB*PP)/128), 256>>>(ln2, W1, hb, bf1, nullptr, BB*PP, CC, FFDIM);
  // 10. xq2 + hb@W2 + bf2
  k_gemm128<1><<<dim3(CC/128, (BB*PP)/128), 256>>>(hb, W2, y, bf2, xq2, BB*PP, FFDIM, CC);
  // 11. (B,P,C) -> (B,C,P) = (B,C,H,W)
  k_transpose<<<dim3(CC/32, PP/32, BB), dim3(32,8)>>>(y, out, PP, CC);
}

// round 12
// speedup vs baseline: 1.4088x; 1.0074x over previous
#include <cuda_runtime.h>
#include <math.h>

#define BB 2
#define CC 256
#define PP 2304      // H*W
#define KDIM 256
#define CLSN 20
#define NKEY 2324    // CLS + NT
#define NHEAD 8
#define HDIM 32
#define FFDIM 1024
#define SN 2336      // padded score row stride (73*32)

// ---------------- scratch (device globals, no allocation) ----------------
__device__ float g_xq [BB*PP*CC];        // transposed x_query (B,P,C)
__device__ float g_qin[BB*PP*CC];        // LN1(xq)
__device__ float g_kin[BB*NKEY*KDIM];    // LN2(x_key)
__device__ float g_q  [BB*PP*CC];        // qin @ Wq
__device__ float g_kv [BB*NKEY*2*CC + 16*512]; // kin @ Wkv (+pad rows, zero)
__device__ float g_ctx[BB*PP*CC];        // attention output (B,P,C)
__device__ float g_xq2[BB*PP*CC];        // xq + ctx@Wp + bp
__device__ float g_ln2[BB*PP*CC];        // LN3(xq2)
__device__ float g_hb [BB*PP*FFDIM];     // gelu(ln2@W1+bf1)
__device__ float g_y  [BB*PP*CC];        // xq2 + hb@W2 + bf2
__device__ float g_S  [(size_t)BB*NHEAD*PP*SN];  // scores / probs (345MB)

// ---------------- helpers ----------------
__device__ __forceinline__ float wsum(float v){
  #pragma unroll
  for (int o=16;o>0;o>>=1) v += __shfl_xor_sync(0xffffffffu, v, o);
  return v;
}
__device__ __forceinline__ float wmax(float v){
  #pragma unroll
  for (int o=16;o>0;o>>=1) v = fmaxf(v, __shfl_xor_sync(0xffffffffu, v, o));
  return v;
}
// exp(x) for x <= 0, FMA-pipe only (no MUFU). ~1e-6 rel error.
__device__ __forceinline__ float fexp(float x){
  x = fmaxf(x, -80.0f);
  float y = x * 1.4426950408889634f;
  float r = y + 12582912.0f;
  float n = r - 12582912.0f;
  float t = (y - n) * 0.6931471805599453f;
  int   i = __float_as_int(r) - 0x4B400000;
  float p = 8.3333338e-3f;
  p = fmaf(p, t, 4.1666668e-2f);
  p = fmaf(p, t, 1.6666667e-1f);
  p = fmaf(p, t, 0.5f);
  p = fmaf(p, t, 1.0f);
  p = fmaf(p, t, 1.0f);
  return p * __int_as_float((i + 127) << 23);
}
// exp(x) for x in [0,1]
__device__ __forceinline__ float exp01(float x){
  float p = 1.9841270e-4f;
  p = fmaf(p, x, 1.3888889e-3f);
  p = fmaf(p, x, 8.3333338e-3f);
  p = fmaf(p, x, 4.1666668e-2f);
  p = fmaf(p, x, 1.6666667e-1f);
  p = fmaf(p, x, 0.5f);
  p = fmaf(p, x, 1.0f);
  p = fmaf(p, x, 1.0f);
  return p;
}
__device__ __forceinline__ float gelu_exact(float x){
  return 0.5f * x * (1.0f + erff(x * 0.70710678118654752f));
}

// ---------------- transpose: in (B,R,Cd) -> out (B,Cd,R) ----------------
__global__ void k_transpose(const float* __restrict__ in, float* __restrict__ out,
                            int R, int Cd){
  __shared__ float tile[32][33];
  int b = blockIdx.z;
  int r0 = blockIdx.y * 32, c0 = blockIdx.x * 32;
  const float* pin = in + (size_t)b * R * Cd;
  float* pout = out + (size_t)b * R * Cd;
  #pragma unroll
  for (int i = threadIdx.y; i < 32; i += 8){
    int r = r0 + i, c = c0 + threadIdx.x;
    if (r < R && c < Cd) tile[i][threadIdx.x] = pin[(size_t)r * Cd + c];
  }
  __syncthreads();
  #pragma unroll
  for (int i = threadIdx.y; i < 32; i += 8){
    int c = c0 + i, r = r0 + threadIdx.x;
    if (c < Cd && r < R) pout[(size_t)c * R + r] = tile[threadIdx.x][i];
  }
}

// ---------------- LayerNorm over last dim 256, one warp per row ----------------
__global__ void k_ln(const float* __restrict__ in, float* __restrict__ out,
                     const float* __restrict__ g, const float* __restrict__ be, int rows){
  int gw = (blockIdx.x * blockDim.x + threadIdx.x) >> 5;
  int lane = threadIdx.x & 31;
  if (gw >= rows) return;
  const float4* p = (const float4*)(in + (size_t)gw * 256);
  float4 a = p[lane];
  float4 b = p[lane + 32];
  float s  = a.x+a.y+a.z+a.w + b.x+b.y+b.z+b.w;
  float ss = a.x*a.x+a.y*a.y+a.z*a.z+a.w*a.w + b.x*b.x+b.y*b.y+b.z*b.z+b.w*b.w;
  s = wsum(s); ss = wsum(ss);
  float mean = s * (1.0f/256.0f);
  float var  = ss * (1.0f/256.0f) - mean*mean;
  float inv  = rsqrtf(var + 1e-5f);
  const float4* g4 = (const float4*)g;
  const float4* b4 = (const float4*)be;
  float4 ga = g4[lane], gb = g4[lane+32];
  float4 ba = b4[lane], bb = b4[lane+32];
  float4 o1, o2;
  o1.x = (a.x-mean)*inv*ga.x + ba.x;  o1.y = (a.y-mean)*inv*ga.y + ba.y;
  o1.z = (a.z-mean)*inv*ga.z + ba.z;  o1.w = (a.w-mean)*inv*ga.w + ba.w;
  o2.x = (b.x-mean)*inv*gb.x + bb.x;  o2.y = (b.y-mean)*inv*gb.y + bb.y;
  o2.z = (b.z-mean)*inv*gb.z + bb.z;  o2.w = (b.w-mean)*inv*gb.w + bb.w;
  float4* po = (float4*)(out + (size_t)gw * 256);
  po[lane] = o1; po[lane + 32] = o2;
}

// ---------------- 128x128 GEMM, 8x8 micro, double-buffered ----------------
// C = A(M,K) @ B(K,N) + epilogue.  N multiple of 128, K multiple of 16, M guarded.
// MODE 0: plain    MODE 1: + bias[col] + resid[idx]    MODE 2: gelu(. + bias[col])
template<int MODE>
__global__ void __launch_bounds__(256) k_gemm128(
    const float* __restrict__ A, const float* __restrict__ Bw,
    float* __restrict__ Co, const float* __restrict__ bias,
    const float* __restrict__ resid, int M, int K, int Nn){
  __shared__ float As[2][16][132];   // transposed: As[k][m]
  __shared__ float Bs[2][16][128];   // Bs[k][n]
  const int bm = blockIdx.y * 128, bn = blockIdx.x * 128;
  const int t = threadIdx.x;
  const int tx = t & 15, ty = t >> 4;
  // A loader coords (2 float4 per thread over 512)
  const int ar0 = t >> 1;                 // wrong mapping avoided: use idx math below
  (void)ar0;
  const int KT = K >> 4;
  float4 pa0, pa1, pb0, pb1;
  const float4 zf4 = make_float4(0.f,0.f,0.f,0.f);

  auto ldA = [&](int kt, int idx, float4& v){
    int row = idx >> 2, kq = idx & 3;
    int gr = bm + row;
    v = (gr < M) ? *(const float4*)(A + (size_t)gr*K + kt*16 + kq*4) : zf4;
  };
  auto ldB = [&](int kt, int idx, float4& v){
    int kr = idx >> 5, col = (idx & 31) * 4;
    v = *(const float4*)(Bw + (size_t)(kt*16 + kr)*Nn + bn + col);
  };
  auto stA = [&](int buf, int idx, const float4& v){
    int row = idx >> 2, kq = (idx & 3) * 4;
    As[buf][kq+0][row] = v.x; As[buf][kq+1][row] = v.y;
    As[buf][kq+2][row] = v.z; As[buf][kq+3][row] = v.w;
  };
  auto stB = [&](int buf, int idx, const float4& v){
    int kr = idx >> 5, col = (idx & 31) * 4;
    *(float4*)&Bs[buf][kr][col] = v;
  };

  float acc[8][8];
  #pragma unroll
  for (int i=0;i<8;i++)
    #pragma unroll
    for (int j=0;j<8;j++) acc[i][j] = 0.f;

  ldA(0, t, pa0); ldA(0, t+256, pa1);
  ldB(0, t, pb0); ldB(0, t+256, pb1);
  stA(0, t, pa0); stA(0, t+256, pa1);
  stB(0, t, pb0); stB(0, t+256, pb1);
  __syncthreads();

  for (int kt = 0; kt < KT; kt++){
    int buf = kt & 1;
    if (kt + 1 < KT){
      ldA(kt+1, t, pa0); ldA(kt+1, t+256, pa1);
      ldB(kt+1, t, pb0); ldB(kt+1, t+256, pb1);
    }
    #pragma unroll
    for (int kk = 0; kk < 16; kk++){
      float4 a0 = *(const float4*)&As[buf][kk][ty*8];
      float4 a1 = *(const float4*)&As[buf][kk][ty*8+4];
      float4 b0 = *(const float4*)&Bs[buf][kk][tx*8];
      float4 b1 = *(const float4*)&Bs[buf][kk][tx*8+4];
      float av[8] = {a0.x,a0.y,a0.z,a0.w,a1.x,a1.y,a1.z,a1.w};
      float bv[8] = {b0.x,b0.y,b0.z,b0.w,b1.x,b1.y,b1.z,b1.w};
      #pragma unroll
      for (int i=0;i<8;i++)
        #pragma unroll
        for (int j=0;j<8;j++) acc[i][j] = fmaf(av[i], bv[j], acc[i][j]);
    }
    if (kt + 1 < KT){
      int nb = buf ^ 1;
      stA(nb, t, pa0); stA(nb, t+256, pa1);
      stB(nb, t, pb0); stB(nb, t+256, pb1);
      __syncthreads();
    }
  }

  // epilogue
  float4 bia0 = zf4, bia1 = zf4;
  if (MODE != 0){
    bia0 = *(const float4*)(bias + bn + tx*8);
    bia1 = *(const float4*)(bias + bn + tx*8 + 4);
  }
  #pragma unroll
  for (int i=0;i<8;i++){
    int gr = bm + ty*8 + i;
    if (gr >= M) continue;
    size_t base = (size_t)gr * Nn + bn + tx*8;
    float4 v0 = make_float4(acc[i][0],acc[i][1],acc[i][2],acc[i][3]);
    float4 v1 = make_float4(acc[i][4],acc[i][5],acc[i][6],acc[i][7]);
    if (MODE == 1){
      float4 r0 = *(const float4*)(resid + base);
      float4 r1 = *(const float4*)(resid + base + 4);
      v0.x += bia0.x + r0.x; v0.y += bia0.y + r0.y; v0.z += bia0.z + r0.z; v0.w += bia0.w + r0.w;
      v1.x += bia1.x + r1.x; v1.y += bia1.y + r1.y; v1.z += bia1.z + r1.z; v1.w += bia1.w + r1.w;
    } else if (MODE == 2){
      v0.x = gelu_exact(v0.x + bia0.x); v0.y = gelu_exact(v0.y + bia0.y);
      v0.z = gelu_exact(v0.z + bia0.z); v0.w = gelu_exact(v0.w + bia0.w);
      v1.x = gelu_exact(v1.x + bia1.x); v1.y = gelu_exact(v1.y + bia1.y);
      v1.z = gelu_exact(v1.z + bia1.z); v1.w = gelu_exact(v1.w + bia1.w);
    }
    *(float4*)(Co + base)     = v0;
    *(float4*)(Co + base + 4) = v1;
  }
}

// ---------------- S = scale * Q K^T per (b,h) ----------------
// grid (ceil(NKEY/128)=19, PP/128=18, 16), block 256. Single K-pass (K=32).
__global__ void __launch_bounds__(256) k_sgemm(){
  __shared__ float Qs[32][132];   // Qs[d][m]
  __shared__ float Ks[32][132];   // Ks[d][j]
  const float SC = 0.17677669529663687f;
  int bh = blockIdx.z;
  int b = bh >> 3, h = bh & 7;
  int bm = blockIdx.y * 128, bj = blockIdx.x * 128;
  int t = threadIdx.x;
  // load tiles: 1024 float4 each, 4 per thread
  #pragma unroll
  for (int i=0;i<4;i++){
    int idx = t + i*256;
    int row = idx >> 3, dq = (idx & 7) * 4;
    float4 qv = *(const float4*)(g_q + ((size_t)(b*PP + bm + row))*CC + h*HDIM + dq);
    Qs[dq+0][row]=qv.x; Qs[dq+1][row]=qv.y; Qs[dq+2][row]=qv.z; Qs[dq+3][row]=qv.w;
    int j = bj + row;
    float4 kv = make_float4(0.f,0.f,0.f,0.f);
    if (j < NKEY) kv = *(const float4*)(g_kv + ((size_t)(b*NKEY + j))*512 + h*HDIM + dq);
    Ks[dq+0][row]=kv.x; Ks[dq+1][row]=kv.y; Ks[dq+2][row]=kv.z; Ks[dq+3][row]=kv.w;
  }
  __syncthreads();
  int tx = t & 15, ty = t >> 4;
  float acc[8][8];
  #pragma unroll
  for (int i=0;i<8;i++)
    #pragma unroll
    for (int j=0;j<8;j++) acc[i][j]=0.f;
  #pragma unroll
  for (int d=0; d<32; d++){
    float4 a0 = *(const float4*)&Qs[d][ty*8];
    float4 a1 = *(const float4*)&Qs[d][ty*8+4];
    float4 b0 = *(const float4*)&Ks[d][tx*8];
    float4 b1 = *(const float4*)&Ks[d][tx*8+4];
    float av[8] = {a0.x,a0.y,a0.z,a0.w,a1.x,a1.y,a1.z,a1.w};
    float bv[8] = {b0.x,b0.y,b0.z,b0.w,b1.x,b1.y,b1.z,b1.w};
    #pragma unroll
    for (int i=0;i<8;i++)
      #pragma unroll
      for (int j=0;j<8;j++) acc[i][j] = fmaf(av[i], bv[j], acc[i][j]);
  }
  // store
  bool fast = (bj + 128 <= NKEY);
  #pragma unroll
  for (int i=0;i<8;i++){
    float* srow = g_S + ((size_t)bh*PP + bm + ty*8 + i)*SN + bj + tx*8;
    if (fast){
      *(float4*)srow     = make_float4(acc[i][0]*SC, acc[i][1]*SC, acc[i][2]*SC, acc[i][3]*SC);
      *(float4*)(srow+4) = make_float4(acc[i][4]*SC, acc[i][5]*SC, acc[i][6]*SC, acc[i][7]*SC);
    } else {
      #pragma unroll
      for (int j=0;j<8;j++){
        int col = bj + tx*8 + j;
        if (col < NKEY) srow[j] = acc[i][j]*SC;
      }
    }
  }
}

// ---------------- softmax stages + mask, in place S -> P ----------------
// one warp per (bh, m) row; grid 4608 blocks x 256.
__global__ void __launch_bounds__(256) k_soft(const float* __restrict__ mask){
  int w = (blockIdx.x * 256 + threadIdx.x) >> 5;
  int lane = threadIdx.x & 31;
  int bh = w / PP, m = w - bh * PP;
  float* srow = g_S + ((size_t)bh*PP + m)*SN;
  // pass 1: maxes
  float v1 = (lane < CLSN) ? srow[lane] : -1e30f;
  float m1 = wmax(v1);
  float mx = -1e30f;
  #pragma unroll 4
  for (int it = 0; it < 72; it++) mx = fmaxf(mx, srow[CLSN + it*32 + lane]);
  mx = wmax(mx);
  // pass 2: denominators
  float d1 = (lane < CLSN) ? fexp(v1 - m1) : 0.f;
  float den1 = wsum(d1);
  float d2 = 0.f;
  #pragma unroll 4
  for (int it = 0; it < 72; it++) d2 += fexp(srow[CLSN + it*32 + lane] - mx);
  float den2 = wsum(d2);
  float inv1 = 1.f/den1, inv2 = 1.f/den2;
  // pass 3: probs -> mask -> exp01
  const float* mrow = mask + ((size_t)bh*NKEY + (CLSN + m))*NKEY;
  float dnf = 0.f;
  for (int it = 0; it < 73; it++){
    int j = it*32 + lane;
    float tv = 0.f;
    if (j < NKEY){
      float s = srow[j];
      float pv = (j < CLSN) ? fexp(s - m1)*inv1 : fexp(s - mx)*inv2;
      tv = (mrow[j] < 0.3f) ? 0.f : exp01(pv);
    }
    srow[j] = tv;
    dnf += tv;
  }
  dnf = wsum(dnf);
  float invf = 1.f/dnf;
  // pass 4: normalize (pads stay 0)
  #pragma unroll 4
  for (int it = 0; it < 73; it++){
    int j = it*32 + lane;
    srow[j] *= invf;
  }
}

// ---------------- ctx = P @ V per (b,h) ----------------
// grid (PP/256=9, 16), block 256. Tile 256m x 32n, K-step 32 (73 tiles over SN).
__global__ void __launch_bounds__(256) k_av(){
  __shared__ float Ps[32][260];   // Ps[k][m]
  __shared__ float Vs[32][36];    // Vs[k][d]
  int bh = blockIdx.y;
  int b = bh >> 3, h = bh & 7;
  int bm = blockIdx.x * 256;
  int t = threadIdx.x;
  int r0 = (t >> 3) * 8;          // row group 0..248
  int nx = (t & 7) * 4;           // col group 0..28
  float acc[8][4];
  #pragma unroll
  for (int i=0;i<8;i++)
    #pragma unroll
    for (int j=0;j<4;j++) acc[i][j]=0.f;

  for (int k0 = 0; k0 < SN; k0 += 32){
    // P tile: 256 rows x 32 k = 2048 float4, 8 per thread
    #pragma unroll
    for (int i=0;i<8;i++){
      int idx = t + i*256;
      int row = idx >> 3, kq = (idx & 7) * 4;
      float4 v = *(const float4*)(g_S + ((size_t)bh*PP + bm + row)*SN + k0 + kq);
      Ps[kq+0][row]=v.x; Ps[kq+1][row]=v.y; Ps[kq+2][row]=v.z; Ps[kq+3][row]=v.w;
    }
    // V tile: 32 rows x 32 d = 256 float4, 1 per thread
    {
      int vr = t >> 3, dq = (t & 7) * 4;
      int j = k0 + vr;
      float4 v = make_float4(0.f,0.f,0.f,0.f);
      if (j < NKEY) v = *(const float4*)(g_kv + ((size_t)(b*NKEY + j))*512 + 256 + h*HDIM + dq);
      *(float4*)&Vs[vr][dq] = v;
    }
    __syncthreads();
    #pragma unroll
    for (int kk=0; kk<32; kk++){
      float4 a0 = *(const float4*)&Ps[kk][r0];
      float4 a1 = *(const float4*)&Ps[kk][r0+4];
      float4 bv = *(const float4*)&Vs[kk][nx];
      float av[8] = {a0.x,a0.y,a0.z,a0.w,a1.x,a1.y,a1.z,a1.w};
      #pragma unroll
      for (int i=0;i<8;i++){
        acc[i][0] = fmaf(av[i], bv.x, acc[i][0]);
        acc[i][1] = fmaf(av[i], bv.y, acc[i][1]);
        acc[i][2] = fmaf(av[i], bv.z, acc[i][2]);
        acc[i][3] = fmaf(av[i], bv.w, acc[i][3]);
      }
    }
    __syncthreads();
  }
  #pragma unroll
  for (int i=0;i<8;i++){
    *(float4*)(g_ctx + ((size_t)(b*PP + bm + r0 + i))*CC + h*HDIM + nx) =
        make_float4(acc[i][0], acc[i][1], acc[i][2], acc[i][3]);
  }
}

// ---------------- launch ----------------
extern "C" void kernel_launch(void* const* d_in, const int* in_sizes, int n_in,
                              void* d_out, int out_size){
  const float* x_query = (const float*)d_in[0];
  const float* x_key   = (const float*)d_in[1];
  const float* mask    = (const float*)d_in[2];
  const float* g1  = (const float*)d_in[3];
  const float* be1 = (const float*)d_in[4];
  const float* g2  = (const float*)d_in[5];
  const float* be2 = (const float*)d_in[6];
  const float* g3  = (const float*)d_in[7];
  const float* be3 = (const float*)d_in[8];
  const float* Wq  = (const float*)d_in[9];
  const float* Wkv = (const float*)d_in[10];
  // d_in[11] = Wcls: unused (CLS query rows are sliced away after Wp)
  const float* Wp  = (const float*)d_in[12];
  const float* bp  = (const float*)d_in[13];
  const float* W1  = (const float*)d_in[14];
  const float* bf1 = (const float*)d_in[15];
  const float* W2  = (const float*)d_in[16];
  const float* bf2 = (const float*)d_in[17];
  float* out = (float*)d_out;

  float *xq,*qin,*kin,*q,*kv,*ctx,*xq2,*ln2,*hb,*y;
  cudaGetSymbolAddress((void**)&xq,  g_xq);
  cudaGetSymbolAddress((void**)&qin, g_qin);
  cudaGetSymbolAddress((void**)&kin, g_kin);
  cudaGetSymbolAddress((void**)&q,   g_q);
  cudaGetSymbolAddress((void**)&kv,  g_kv);
  cudaGetSymbolAddress((void**)&ctx, g_ctx);
  cudaGetSymbolAddress((void**)&xq2, g_xq2);
  cudaGetSymbolAddress((void**)&ln2, g_ln2);
  cudaGetSymbolAddress((void**)&hb,  g_hb);
  cudaGetSymbolAddress((void**)&y,   g_y);

  // 1. (B,C,P) -> (B,P,C)
  k_transpose<<<dim3(PP/32, CC/32, BB), dim3(32,8)>>>(x_query, xq, CC, PP);
  // 2-3. LayerNorms
  k_ln<<<(BB*PP)/8, 256>>>(xq, qin, g1, be1, BB*PP);
  k_ln<<<(BB*NKEY+7)/8, 256>>>(x_key, kin, g2, be2, BB*NKEY);
  // 4-5. q / kv projections
  k_gemm128<0><<<dim3(CC/128,    (BB*PP)/128),      256>>>(qin, Wq,  q,  nullptr, nullptr, BB*PP,   CC,   CC);
  k_gemm128<0><<<dim3((2*CC)/128,(BB*NKEY+127)/128),256>>>(kin, Wkv, kv, nullptr, nullptr, BB*NKEY, KDIM, 2*CC);
  // 6a. S = scale Q K^T
  k_sgemm<<<dim3((NKEY+127)/128, PP/128, BB*NHEAD), 256>>>();
  // 6b. softmax stages + mask (in place)
  k_soft<<<(BB*NHEAD*PP)/8, 256>>>(mask);
  // 6c. ctx = P V
  k_av<<<dim3(PP/256, BB*NHEAD), 256>>>();
  // 7. ctx@Wp + bp + xq  -> xq2
  k_gemm128<1><<<dim3(CC/128, (BB*PP)/128), 256>>>(ctx, Wp, xq2, bp, xq, BB*PP, CC, CC);
  // 8. LN3
  k_ln<<<(BB*PP)/8, 256>>>(xq2, ln2, g3, be3, BB*PP);
  // 9. gelu(ln2@W1 + bf1)
  k_gemm128<2><<<dim3(FFDIM/128, (BB*PP)/128), 256>>>(ln2, W1, hb, bf1, nullptr, BB*PP, CC, FFDIM);
  // 10. xq2 + hb@W2 + bf2
  k_gemm128<1><<<dim3(CC/128, (BB*PP)/128), 256>>>(hb, W2, y, bf2, xq2, BB*PP, FFDIM, CC);
  // 11. (B,P,C) -> (B,C,P) = (B,C,H,W)
  k_transpose<<<dim3(CC/32, PP/32, BB), dim3(32,8)>>>(y, out, PP, CC);
}

// round 15
// speedup vs baseline: 2.8263x; 2.0062x over previous
#include <cuda_runtime.h>
#include <cuda_bf16.h>
#include <cstdint>
#include <math.h>

#define BB 2
#define CC 256
#define PP 2304
#define KDIM 256
#define CLSN 20
#define NKEY 2324
#define NHEAD 8
#define HDIM 32
#define FFDIM 1024
#define SN 2336

// ---------------- scratch ----------------
__device__ float g_xq [BB*PP*CC];
__device__ float g_qin[BB*PP*CC];
__device__ float g_kin[BB*NKEY*KDIM];
__device__ float g_q  [BB*PP*CC];
__device__ float g_kv [BB*NKEY*2*CC + 16*512];
__device__ float g_ctx[BB*PP*CC];
__device__ float g_xq2[BB*PP*CC];
__device__ float g_ln2[BB*PP*CC];
__device__ float g_hb [BB*PP*FFDIM];
__device__ float g_y  [BB*PP*CC];
__device__ __nv_bfloat16 g_Sb[(size_t)BB*NHEAD*PP*SN];  // scores bf16
__device__ __nv_bfloat16 g_P [(size_t)BB*NHEAD*PP*SN];  // probs  bf16

// ---------------- helpers ----------------
__device__ __forceinline__ float wsum(float v){
  #pragma unroll
  for (int o=16;o>0;o>>=1) v += __shfl_xor_sync(0xffffffffu, v, o);
  return v;
}
__device__ __forceinline__ float wmax(float v){
  #pragma unroll
  for (int o=16;o>0;o>>=1) v = fmaxf(v, __shfl_xor_sync(0xffffffffu, v, o));
  return v;
}
__device__ __forceinline__ float fexp(float x){  // exp, x<=0, FMA pipe
  x = fmaxf(x, -80.0f);
  float y = x * 1.4426950408889634f;
  float r = y + 12582912.0f;
  float n = r - 12582912.0f;
  float t = (y - n) * 0.6931471805599453f;
  int   i = __float_as_int(r) - 0x4B400000;
  float p = 8.3333338e-3f;
  p = fmaf(p, t, 4.1666668e-2f);
  p = fmaf(p, t, 1.6666667e-1f);
  p = fmaf(p, t, 0.5f);
  p = fmaf(p, t, 1.0f);
  p = fmaf(p, t, 1.0f);
  return p * __int_as_float((i + 127) << 23);
}
__device__ __forceinline__ float exp01(float x){ // exp, x in [0,1]
  float p = 1.9841270e-4f;
  p = fmaf(p, x, 1.3888889e-3f);
  p = fmaf(p, x, 8.3333338e-3f);
  p = fmaf(p, x, 4.1666668e-2f);
  p = fmaf(p, x, 1.6666667e-1f);
  p = fmaf(p, x, 0.5f);
  p = fmaf(p, x, 1.0f);
  p = fmaf(p, x, 1.0f);
  return p;
}
__device__ __forceinline__ float gelu_exact(float x){
  return 0.5f * x * (1.0f + erff(x * 0.70710678118654752f));
}
__device__ __forceinline__ float f2tff(float x){
  uint32_t r; asm("cvt.rna.tf32.f32 %0, %1;" : "=r"(r) : "f"(x));
  return __uint_as_float(r);
}
__device__ __forceinline__ float4 cvt4(float4 v){
  return make_float4(f2tff(v.x), f2tff(v.y), f2tff(v.z), f2tff(v.w));
}
__device__ __forceinline__ uint32_t fbits(float x){ return __float_as_uint(x); }
__device__ __forceinline__ void mma_tf32(float* c, const uint32_t* a, const uint32_t* b){
  asm volatile("mma.sync.aligned.m16n8k8.row.col.f32.tf32.tf32.f32 "
    "{%0,%1,%2,%3}, {%4,%5,%6,%7}, {%8,%9}, {%0,%1,%2,%3};"
    : "+f"(c[0]),"+f"(c[1]),"+f"(c[2]),"+f"(c[3])
    : "r"(a[0]),"r"(a[1]),"r"(a[2]),"r"(a[3]), "r"(b[0]),"r"(b[1]));
}
__device__ __forceinline__ void mma_bf16(float* c, const uint32_t* a, const uint32_t* b){
  asm volatile("mma.sync.aligned.m16n8k16.row.col.f32.bf16.bf16.f32 "
    "{%0,%1,%2,%3}, {%4,%5,%6,%7}, {%8,%9}, {%0,%1,%2,%3};"
    : "+f"(c[0]),"+f"(c[1]),"+f"(c[2]),"+f"(c[3])
    : "r"(a[0]),"r"(a[1]),"r"(a[2]),"r"(a[3]), "r"(b[0]),"r"(b[1]));
}

// ---------------- transpose (B,R,Cd) -> (B,Cd,R) ----------------
__global__ void k_transpose(const float* __restrict__ in, float* __restrict__ out,
                            int R, int Cd){
  __shared__ float tile[32][33];
  int b = blockIdx.z;
  int r0 = blockIdx.y * 32, c0 = blockIdx.x * 32;
  const float* pin = in + (size_t)b * R * Cd;
  float* pout = out + (size_t)b * R * Cd;
  #pragma unroll
  for (int i = threadIdx.y; i < 32; i += 8){
    int r = r0 + i, c = c0 + threadIdx.x;
    if (r < R && c < Cd) tile[i][threadIdx.x] = pin[(size_t)r * Cd + c];
  }
  __syncthreads();
  #pragma unroll
  for (int i = threadIdx.y; i < 32; i += 8){
    int c = c0 + i, r = r0 + threadIdx.x;
    if (c < Cd && r < R) pout[(size_t)c * R + r] = tile[threadIdx.x][i];
  }
}

// ---------------- LayerNorm (last dim 256), one warp/row ----------------
__global__ void k_ln(const float* __restrict__ in, float* __restrict__ out,
                     const float* __restrict__ g, const float* __restrict__ be, int rows){
  int gw = (blockIdx.x * blockDim.x + threadIdx.x) >> 5;
  int lane = threadIdx.x & 31;
  if (gw >= rows) return;
  const float4* p = (const float4*)(in + (size_t)gw * 256);
  float4 a = p[lane];
  float4 b = p[lane + 32];
  float s  = a.x+a.y+a.z+a.w + b.x+b.y+b.z+b.w;
  float ss = a.x*a.x+a.y*a.y+a.z*a.z+a.w*a.w + b.x*b.x+b.y*b.y+b.z*b.z+b.w*b.w;
  s = wsum(s); ss = wsum(ss);
  float mean = s * (1.0f/256.0f);
  float var  = ss * (1.0f/256.0f) - mean*mean;
  float inv  = rsqrtf(var + 1e-5f);
  const float4* g4 = (const float4*)g;
  const float4* b4 = (const float4*)be;
  float4 ga = g4[lane], gb = g4[lane+32];
  float4 ba = b4[lane], bb = b4[lane+32];
  float4 o1, o2;
  o1.x = (a.x-mean)*inv*ga.x + ba.x;  o1.y = (a.y-mean)*inv*ga.y + ba.y;
  o1.z = (a.z-mean)*inv*ga.z + ba.z;  o1.w = (a.w-mean)*inv*ga.w + ba.w;
  o2.x = (b.x-mean)*inv*gb.x + bb.x;  o2.y = (b.y-mean)*inv*gb.y + bb.y;
  o2.z = (b.z-mean)*inv*gb.z + bb.z;  o2.w = (b.w-mean)*inv*gb.w + bb.w;
  float4* po = (float4*)(out + (size_t)gw * 256);
  po[lane] = o1; po[lane + 32] = o2;
}

// ---------------- tf32 MMA GEMM: 128x64 CTA tile, BK=16, double buffered ----
// 8 warps: (wid&3)->32 m-rows, (wid>>2)->32 n-cols. N%64==0, K%16==0, M guarded.
// MODE 0: plain  MODE 1: +bias+resid  MODE 2: gelu(.+bias)
template<int MODE>
__global__ void __launch_bounds__(256) k_gemmT(
    const float* __restrict__ A, const float* __restrict__ Bw,
    float* __restrict__ Co, const float* __restrict__ bias,
    const float* __restrict__ resid, int M, int K, int Nn){
  __shared__ float As[2][128][20];   // [m][k]
  __shared__ float Bs[2][16][72];    // [k][n]
  const int bm = blockIdx.y*128, bn = blockIdx.x*64;
  const int t = threadIdx.x, wid = t>>5, lane = t&31, g = lane>>2, tig = lane&3;
  const int wm = (wid&3)*32, wn = (wid>>2)*32;
  const int KT = K >> 4;
  const float4 zf4 = make_float4(0.f,0.f,0.f,0.f);
  float4 ra[2], rb;
  float acc[2][4][4];
  #pragma unroll
  for (int i=0;i<2;i++)
    #pragma unroll
    for (int j=0;j<4;j++)
      #pragma unroll
      for (int k=0;k<4;k++) acc[i][j][k]=0.f;

  auto LDG = [&](int kt){
    #pragma unroll
    for (int i=0;i<2;i++){
      int idx = t + i*256, row = idx>>2, kq = (idx&3)*4, gr = bm+row;
      ra[i] = (gr < M) ? *(const float4*)(A + (size_t)gr*K + kt*16 + kq) : zf4;
    }
    int kr = t>>4, nq = (t&15)*4;
    rb = *(const float4*)(Bw + (size_t)(kt*16+kr)*Nn + bn + nq);
  };
  auto STS = [&](int buf){
    #pragma unroll
    for (int i=0;i<2;i++){
      int idx = t + i*256, row = idx>>2, kq = (idx&3)*4;
      *(float4*)&As[buf][row][kq] = cvt4(ra[i]);
    }
    int kr = t>>4, nq = (t&15)*4;
    *(float4*)&Bs[buf][kr][nq] = cvt4(rb);
  };

  LDG(0); STS(0);
  __syncthreads();
  for (int kt=0; kt<KT; kt++){
    int buf = kt & 1;
    if (kt+1 < KT) LDG(kt+1);
    #pragma unroll
    for (int k8=0;k8<2;k8++){
      int kb = k8*8;
      uint32_t af[2][4];
      #pragma unroll
      for (int mt=0;mt<2;mt++){
        int mr = wm + mt*16 + g;
        af[mt][0] = fbits(As[buf][mr  ][kb+tig]);
        af[mt][1] = fbits(As[buf][mr+8][kb+tig]);
        af[mt][2] = fbits(As[buf][mr  ][kb+tig+4]);
        af[mt][3] = fbits(As[buf][mr+8][kb+tig+4]);
      }
      #pragma unroll
      for (int nt=0;nt<4;nt++){
        int nc = wn + nt*8 + g;
        uint32_t bf[2];
        bf[0] = fbits(Bs[buf][kb+tig  ][nc]);
        bf[1] = fbits(Bs[buf][kb+tig+4][nc]);
        mma_tf32(acc[0][nt], af[0], bf);
        mma_tf32(acc[1][nt], af[1], bf);
      }
    }
    if (kt+1 < KT){ STS(buf^1); __syncthreads(); }
  }

  #pragma unroll
  for (int mt=0;mt<2;mt++){
    int r0 = bm + wm + mt*16 + g, r1 = r0 + 8;
    #pragma unroll
    for (int nt=0;nt<4;nt++){
      int col = bn + wn + nt*8 + tig*2;
      float2 v0 = make_float2(acc[mt][nt][0], acc[mt][nt][1]);
      float2 v1 = make_float2(acc[mt][nt][2], acc[mt][nt][3]);
      if (MODE == 1){
        float2 bb = *(const float2*)(bias + col);
        if (r0 < M){
          float2 rr = *(const float2*)(resid + (size_t)r0*Nn + col);
          v0.x += bb.x + rr.x; v0.y += bb.y + rr.y;
        }
        if (r1 < M){
          float2 rr = *(const float2*)(resid + (size_t)r1*Nn + col);
          v1.x += bb.x + rr.x; v1.y += bb.y + rr.y;
        }
      } else if (MODE == 2){
        float2 bb = *(const float2*)(bias + col);
        v0.x = gelu_exact(v0.x + bb.x); v0.y = gelu_exact(v0.y + bb.y);
        v1.x = gelu_exact(v1.x + bb.x); v1.y = gelu_exact(v1.y + bb.y);
      }
      if (r0 < M) *(float2*)(Co + (size_t)r0*Nn + col) = v0;
      if (r1 < M) *(float2*)(Co + (size_t)r1*Nn + col) = v1;
    }
  }
}

// ---------------- S = scale*Q K^T (tf32 mma), bf16 out ----------------
// grid (19,18,16), 256 thr; tile 128m x 128j, single K=32 pass.
__global__ void __launch_bounds__(256) k_sgemm(){
  __shared__ float Qs[128][36];
  __shared__ float Ks[128][36];
  const float SC = 0.17677669529663687f;
  int bh = blockIdx.z, b = bh>>3, h = bh&7;
  int bm = blockIdx.y*128, bj = blockIdx.x*128;
  int t = threadIdx.x, wid = t>>5, lane = t&31, g = lane>>2, tig = lane&3;
  int wm = (wid&3)*32, wn = (wid>>2)*64;
  #pragma unroll
  for (int i=0;i<4;i++){
    int idx = t + i*256, row = idx>>3, dq = (idx&7)*4;
    float4 qv = *(const float4*)(g_q + ((size_t)(b*PP+bm+row))*CC + h*HDIM + dq);
    *(float4*)&Qs[row][dq] = cvt4(qv);
    int j = bj + row;
    float4 kv4 = make_float4(0.f,0.f,0.f,0.f);
    if (j < NKEY) kv4 = *(const float4*)(g_kv + ((size_t)(b*NKEY+j))*512 + h*HDIM + dq);
    *(float4*)&Ks[row][dq] = cvt4(kv4);
  }
  __syncthreads();
  float acc[2][8][4];
  #pragma unroll
  for (int i=0;i<2;i++)
    #pragma unroll
    for (int j=0;j<8;j++)
      #pragma unroll
      for (int k=0;k<4;k++) acc[i][j][k]=0.f;
  #pragma unroll
  for (int k8=0;k8<4;k8++){
    int kb = k8*8;
    uint32_t af[2][4];
    #pragma unroll
    for (int mt=0;mt<2;mt++){
      int mr = wm + mt*16 + g;
      af[mt][0] = fbits(Qs[mr  ][kb+tig]);
      af[mt][1] = fbits(Qs[mr+8][kb+tig]);
      af[mt][2] = fbits(Qs[mr  ][kb+tig+4]);
      af[mt][3] = fbits(Qs[mr+8][kb+tig+4]);
    }
    #pragma unroll
    for (int nt=0;nt<8;nt++){
      int jc = wn + nt*8 + g;
      uint32_t bf[2];
      bf[0] = fbits(Ks[jc][kb+tig]);
      bf[1] = fbits(Ks[jc][kb+tig+4]);
      mma_tf32(acc[0][nt], af[0], bf);
      mma_tf32(acc[1][nt], af[1], bf);
    }
  }
  __nv_bfloat16* Sb = g_Sb + (size_t)bh*PP*SN;
  #pragma unroll
  for (int mt=0;mt<2;mt++){
    int r0 = bm + wm + mt*16 + g, r1 = r0 + 8;
    #pragma unroll
    for (int nt=0;nt<8;nt++){
      int col = bj + wn + nt*8 + tig*2;
      if (col < NKEY){   // NKEY even -> pair never straddles
        *(__nv_bfloat162*)(Sb + (size_t)r0*SN + col) =
            __floats2bfloat162_rn(acc[mt][nt][0]*SC, acc[mt][nt][1]*SC);
        *(__nv_bfloat162*)(Sb + (size_t)r1*SN + col) =
            __floats2bfloat162_rn(acc[mt][nt][2]*SC, acc[mt][nt][3]*SC);
      }
    }
  }
}

// ---------------- softmax stages + mask: bf16 S -> bf16 P ----------------
// One warp per row, 2 keys/lane via bf162. Lanes only re-read their own
// stores -> no syncs. exp computed once. grid 4608 x 256.
__global__ void __launch_bounds__(256) k_soft(const float* __restrict__ mask){
  int lane = threadIdx.x & 31;
  int row = blockIdx.x*8 + (threadIdx.x>>5);
  int bh = row / PP, m = row - bh*PP;
  const __nv_bfloat16* srow = g_Sb + (size_t)row*SN;
  __nv_bfloat16* prow = g_P + (size_t)row*SN;
  // pass 1: segment maxes
  float s0c = -1e30f, s1c = -1e30f;
  if (lane < 10){
    __nv_bfloat162 p = *(const __nv_bfloat162*)(srow + lane*2);
    s0c = __bfloat162float(p.x); s1c = __bfloat162float(p.y);
  }
  float m1 = wmax(fmaxf(s0c, s1c));
  float mx = -1e30f;
  for (int it=0; it<37; it++){
    int base = (it*32 + lane)*2;
    if (base >= CLSN && base < NKEY){
      __nv_bfloat162 p = *(const __nv_bfloat162*)(srow + base);
      mx = fmaxf(mx, fmaxf(__bfloat162float(p.x), __bfloat162float(p.y)));
    }
  }
  mx = wmax(mx);
  // pass 2: e + denominators (store e)
  float d1 = 0.f;
  if (lane < 10){
    float e0 = fexp(s0c - m1), e1 = fexp(s1c - m1);
    d1 = e0 + e1;
    *(__nv_bfloat162*)(prow + lane*2) = __floats2bfloat162_rn(e0, e1);
  }
  float den1 = wsum(d1);
  float d2 = 0.f;
  for (int it=0; it<37; it++){
    int base = (it*32 + lane)*2;
    if (base >= CLSN && base < NKEY){
      __nv_bfloat162 p = *(const __nv_bfloat162*)(srow + base);
      float e0 = fexp(__bfloat162float(p.x) - mx);
      float e1 = fexp(__bfloat162float(p.y) - mx);
      d2 += e0 + e1;
      *(__nv_bfloat162*)(prow + base) = __floats2bfloat162_rn(e0, e1);
    }
  }
  float den2 = wsum(d2);
  float inv1 = 1.f/den1, inv2 = 1.f/den2;
  // pass 3: mask + exp01 (store t)
  const float* mrow = mask + ((size_t)bh*NKEY + (CLSN + m))*NKEY;
  float dnf = 0.f;
  for (int it=0; it<37; it++){
    int base = (it*32 + lane)*2;
    if (base < NKEY){
      __nv_bfloat162 p = *(const __nv_bfloat162*)(prow + base);
      float2 mk = *(const float2*)(mrow + base);
      float inv = (base < CLSN) ? inv1 : inv2;
      float t0 = 0.f, t1 = 0.f;
      if (mk.x >= 0.3f) t0 = exp01(__bfloat162float(p.x) * inv);
      if (mk.y >= 0.3f) t1 = exp01(__bfloat162float(p.y) * inv);
      dnf += t0 + t1;
      *(__nv_bfloat162*)(prow + base) = __floats2bfloat162_rn(t0, t1);
    }
  }
  dnf = wsum(dnf);
  float invf = 1.f/dnf;
  // pass 4: normalize; zero pads [NKEY, SN)
  for (int it=0; it<37; it++){
    int base = (it*32 + lane)*2;
    if (base < SN){
      float t0 = 0.f, t1 = 0.f;
      if (base < NKEY){
        __nv_bfloat162 p = *(const __nv_bfloat162*)(prow + base);
        t0 = __bfloat162float(p.x) * invf;
        t1 = __bfloat162float(p.y) * invf;
      }
      *(__nv_bfloat162*)(prow + base) = __floats2bfloat162_rn(t0, t1);
    }
  }
}

// ---------------- ctx = P @ V (bf16 mma) ----------------
// grid (18,16), 256 thr; tile 128m x 32d, K-tile 64, double buffered.
__global__ void __launch_bounds__(256) k_av(){
  __shared__ __nv_bfloat16 Ps[2][128][72];   // [m][k]
  __shared__ __nv_bfloat16 Vs[2][32][72];    // [d][k]  (V transposed)
  int bh = blockIdx.y, b = bh>>3, h = bh&7;
  int bm = blockIdx.x*128;
  int t = threadIdx.x, wid = t>>5, lane = t&31, g = lane>>2, tig = lane&3;
  const __nv_bfloat16* Pb = g_P + ((size_t)bh*PP + bm)*SN;
  uint2 rp[8]; float rv[8];
  auto LDG = [&](int kt){
    int k0 = kt*64;
    #pragma unroll
    for (int i=0;i<8;i++){
      int idx = t + i*256, rowm = idx>>4, q4 = (idx&15)*4;
      int col = k0 + q4;
      rp[i] = (col < SN) ? *(const uint2*)(Pb + (size_t)rowm*SN + col)
                         : make_uint2(0u,0u);
    }
    #pragma unroll
    for (int i=0;i<8;i++){
      int idx = t + i*256, j = idx>>5, d = idx&31;
      int jj = k0 + j;
      rv[i] = (jj < NKEY) ? g_kv[((size_t)(b*NKEY + jj))*512 + 256 + h*HDIM + d] : 0.f;
    }
  };
  auto STS = [&](int buf){
    #pragma unroll
    for (int i=0;i<8;i++){
      int idx = t + i*256, rowm = idx>>4, q4 = (idx&15)*4;
      *(uint2*)&Ps[buf][rowm][q4] = rp[i];
    }
    #pragma unroll
    for (int i=0;i<8;i++){
      int idx = t + i*256, j = idx>>5, d = idx&31;
      Vs[buf][d][j] = __float2bfloat16(rv[i]);
    }
  };
  float acc[4][4];
  #pragma unroll
  for (int i=0;i<4;i++)
    #pragma unroll
    for (int j=0;j<4;j++) acc[i][j]=0.f;

  const int KT = (SN + 63)/64;   // 37
  LDG(0); STS(0);
  __syncthreads();
  for (int kt=0; kt<KT; kt++){
    int buf = kt & 1;
    if (kt+1 < KT) LDG(kt+1);
    #pragma unroll
    for (int k16=0;k16<4;k16++){
      int kb = k16*16;
      int mr = wid*16 + g;
      uint32_t af[4];
      af[0] = *(const uint32_t*)&Ps[buf][mr  ][kb + 2*tig];
      af[1] = *(const uint32_t*)&Ps[buf][mr+8][kb + 2*tig];
      af[2] = *(const uint32_t*)&Ps[buf][mr  ][kb + 2*tig + 8];
      af[3] = *(const uint32_t*)&Ps[buf][mr+8][kb + 2*tig + 8];
      #pragma unroll
      for (int nt=0;nt<4;nt++){
        int nc = nt*8 + g;
        uint32_t bf[2];
        bf[0] = *(const uint32_t*)&Vs[buf][nc][kb + 2*tig];
        bf[1] = *(const uint32_t*)&Vs[buf][nc][kb + 2*tig + 8];
        mma_bf16(acc[nt], af, bf);
      }
    }
    if (kt+1 < KT){ STS(buf^1); __syncthreads(); }
  }
  int m0 = bm + wid*16 + g;
  #pragma unroll
  for (int nt=0;nt<4;nt++){
    int d = nt*8 + tig*2;
    *(float2*)(g_ctx + ((size_t)(b*PP + m0    ))*CC + h*HDIM + d) =
        make_float2(acc[nt][0], acc[nt][1]);
    *(float2*)(g_ctx + ((size_t)(b*PP + m0 + 8))*CC + h*HDIM + d) =
        make_float2(acc[nt][2], acc[nt][3]);
  }
}

// ---------------- launch ----------------
extern "C" void kernel_launch(void* const* d_in, const int* in_sizes, int n_in,
                              void* d_out, int out_size){
  const float* x_query = (const float*)d_in[0];
  const float* x_key   = (const float*)d_in[1];
  const float* mask    = (const float*)d_in[2];
  const float* g1  = (const float*)d_in[3];
  const float* be1 = (const float*)d_in[4];
  const float* g2  = (const float*)d_in[5];
  const float* be2 = (const float*)d_in[6];
  const float* g3  = (const float*)d_in[7];
  const float* be3 = (const float*)d_in[8];
  const float* Wq  = (const float*)d_in[9];
  const float* Wkv = (const float*)d_in[10];
  // d_in[11] = Wcls: unused (CLS query rows are sliced away after Wp)
  const float* Wp  = (const float*)d_in[12];
  const float* bp  = (const float*)d_in[13];
  const float* W1  = (const float*)d_in[14];
  const float* bf1 = (const float*)d_in[15];
  const float* W2  = (const float*)d_in[16];
  const float* bf2 = (const float*)d_in[17];
  float* out = (float*)d_out;

  float *xq,*qin,*kin,*q,*kv,*ctx,*xq2,*ln2,*hb,*y;
  cudaGetSymbolAddress((void**)&xq,  g_xq);
  cudaGetSymbolAddress((void**)&qin, g_qin);
  cudaGetSymbolAddress((void**)&kin, g_kin);
  cudaGetSymbolAddress((void**)&q,   g_q);
  cudaGetSymbolAddress((void**)&kv,  g_kv);
  cudaGetSymbolAddress((void**)&ctx, g_ctx);
  cudaGetSymbolAddress((void**)&xq2, g_xq2);
  cudaGetSymbolAddress((void**)&ln2, g_ln2);
  cudaGetSymbolAddress((void**)&hb,  g_hb);
  cudaGetSymbolAddress((void**)&y,   g_y);

  // 1. (B,C,P) -> (B,P,C)
  k_transpose<<<dim3(PP/32, CC/32, BB), dim3(32,8)>>>(x_query, xq, CC, PP);
  // 2-3. LayerNorms
  k_ln<<<(BB*PP)/8, 256>>>(xq, qin, g1, be1, BB*PP);
  k_ln<<<(BB*NKEY+7)/8, 256>>>(x_key, kin, g2, be2, BB*NKEY);
  // 4-5. projections (tf32 MMA)
  k_gemmT<0><<<dim3(CC/64,    (BB*PP)/128),       256>>>(qin, Wq,  q,  nullptr, nullptr, BB*PP,   CC,   CC);
  k_gemmT<0><<<dim3((2*CC)/64,(BB*NKEY+127)/128), 256>>>(kin, Wkv, kv, nullptr, nullptr, BB*NKEY, KDIM, 2*CC);
  // 6a. S = scale Q K^T (tf32 MMA, bf16 out)
  k_sgemm<<<dim3((NKEY+127)/128, PP/128, BB*NHEAD), 256>>>();
  // 6b. softmax stages + mask (bf16 in/out)
  k_soft<<<(BB*NHEAD*PP)/8, 256>>>(mask);
  // 6c. ctx = P V (bf16 MMA)
  k_av<<<dim3(PP/128, BB*NHEAD), 256>>>();
  // 7. ctx@Wp + bp + xq
  k_gemmT<1><<<dim3(CC/64, (BB*PP)/128), 256>>>(ctx, Wp, xq2, bp, xq, BB*PP, CC, CC);
  // 8. LN3
  k_ln<<<(BB*PP)/8, 256>>>(xq2, ln2, g3, be3, BB*PP);
  // 9. gelu(ln2@W1 + bf1)
  k_gemmT<2><<<dim3(FFDIM/64, (BB*PP)/128), 256>>>(ln2, W1, hb, bf1, nullptr, BB*PP, CC, FFDIM);
  // 10. xq2 + hb@W2 + bf2
  k_gemmT<1><<<dim3(CC/64, (BB*PP)/128), 256>>>(hb, W2, y, bf2, xq2, BB*PP, FFDIM, CC);
  // 11. (B,P,C) -> (B,C,H,W)
  k_transpose<<<dim3(CC/32, PP/32, BB), dim3(32,8)>>>(y, out, PP, CC);
}